// round 12
// baseline (speedup 1.0000x reference)
#include <cuda_runtime.h>
#include <cuda_fp16.h>
#include <cstdint>

// DeformableFusionAcrossFocus R11: split-site warps (2 warps/site), 1024-thr CTA,
// 32 warps/SM @ <=64 regs. Two-stage HMMA with smem za exchange for stage-2 k=16.
// Stage 1 (warp = (site, tt)): Z^T[m, n' in tt-half] = sum_c W[m,c] * X[c,n']
// Stage 2: out[o, n in tt-half] += Z^T[o, s(0..15)] * G[s,n]  (za halves exchanged via smem)

#define HW 9216
#define NWF 1792     // 14 oc-groups * 4 ks * 32 lanes

// ---- smem byte layout ----
#define SM_WF    0        // weight A-frags = 28672
#define SM_SCR   28672    // X staging 70656B; reused as EXZ (32KB) then STG2 (64KB)
#define SM_ZOF   99328    // per-site offset rows: 16 * 384 floats = 24576
#define SM_CB    123904   // coeff tables: W0[768] W1[768] S[768] = 9216
#define SM_BD    133120   // 64 floats
#define SM_BO    133376   // 6 floats (+pad)
#define SMEM_TOTAL 133408

__device__ uint4 g_WF[NWF];

__device__ __forceinline__ void mma16816(float& d0, float& d1, float& d2, float& d3,
                                         uint4 a, uint2 b) {
    asm volatile(
        "mma.sync.aligned.m16n8k16.row.col.f32.f16.f16.f32 "
        "{%0,%1,%2,%3}, {%4,%5,%6,%7}, {%8,%9}, {%0,%1,%2,%3};"
        : "+f"(d0), "+f"(d1), "+f"(d2), "+f"(d3)
        : "r"(a.x), "r"(a.y), "r"(a.z), "r"(a.w), "r"(b.x), "r"(b.y));
}

__device__ __forceinline__ uint32_t pk16(float vlo, float vhi) {
    uint32_t r;
    asm("cvt.rn.f16x2.f32 %0, %1, %2;" : "=r"(r) : "f"(vhi), "f"(vlo));
    return r;
}
__device__ __forceinline__ float2 h2f2(uint32_t h) {
    __half2 hh = *reinterpret_cast<__half2*>(&h);
    return __half22float2(hh);
}

__device__ __forceinline__ float wval(int m, int c,
                                      const float* __restrict__ w_def,
                                      const float* __restrict__ w_off) {
    if (m < 192) { int kk = m >> 6, o = m & 63; return __ldg(w_def + o * 192 + c * 3 + kk); }
    if (m < 210) { int t = m - 192; int kk = t / 6, j = t - 6 * kk;
                   return __ldg(w_off + j * 192 + c * 3 + kk); }
    return 0.f;
}

// ---------------- prep: build weight A-fragments once ----------------
__global__ void deform_prep_kernel(const float* __restrict__ w_off,
                                   const float* __restrict__ w_def)
{
    int idx = blockIdx.x * blockDim.x + threadIdx.x;
    if (idx >= NWF) return;
    int l = idx & 31, rem = idx >> 5;
    int ks = rem & 3, oc = rem >> 2;
    int qq = l & 3, gg = l >> 2;
    int c0 = ks * 16 + qq * 2;
    int m0 = oc * 16 + gg, m1 = m0 + 8;
    uint32_t a0 = pk16(wval(m0, c0,     w_def, w_off), wval(m0, c0 + 1, w_def, w_off));
    uint32_t a1 = pk16(wval(m1, c0,     w_def, w_off), wval(m1, c0 + 1, w_def, w_off));
    uint32_t a2 = pk16(wval(m0, c0 + 8, w_def, w_off), wval(m0, c0 + 9, w_def, w_off));
    uint32_t a3 = pk16(wval(m1, c0 + 8, w_def, w_off), wval(m1, c0 + 9, w_def, w_off));
    g_WF[(oc * 4 + ks) * 32 + l] = make_uint4(a0, a1, a2, a3);
}

__global__ void __launch_bounds__(1024, 1)
deform_hmma9_kernel(const float* __restrict__ x,
                    const float* __restrict__ b_off,
                    const float* __restrict__ b_def,
                    float* __restrict__ out)
{
    extern __shared__ char smem[];
    uint4*  WF   = (uint4*)(smem + SM_WF);
    float*  SCR  = (float*)(smem + SM_SCR);
    float*  ZOF  = (float*)(smem + SM_ZOF);
    float*  CBW0 = (float*)(smem + SM_CB);
    float*  CBW1 = CBW0 + 768;
    int*    CBS  = (int*)(CBW1 + 768);
    float*  BD   = (float*)(smem + SM_BD);
    float*  BO   = (float*)(smem + SM_BO);

    const int tid  = threadIdx.x;
    const int wid  = tid >> 5;
    const int lane = tid & 31;
    const int site = wid >> 1;       // local w-site 0..15
    const int tt   = wid & 1;        // n/n' half
    const int g    = lane >> 2;
    const int q    = lane & 3;
    const int nn   = tt * 8 + g;     // this warp's fragment column row

    const int bid = blockIdx.x;      // 0..1151
    const int b   = bid / 576;
    const int h   = (bid / 6) % 96;
    const int w0  = (bid % 6) * 16;
    const long xbase = (long)b * (64 * 16 * HW) + (long)h * 96 + w0;

    if (tid < 64) BD[tid] = b_def[tid];
    if (tid < 6)  BO[tid] = b_off[tid];

    // ---------------- stage X[c][s][n] -> SCR[c*276 + s*17 + n] ----------------
    {
        const float* xb = x + xbase;
        #pragma unroll 16
        for (int i = tid; i < 16384; i += 1024) {
            int s = i & 15, n = (i >> 4) & 15, c = i >> 8;
            SCR[c * 276 + s * 17 + n] = xb[(long)(c * 16 + n) * HW + s];
        }
    }
    // ---------------- weight A-fragments: coalesced copy ----------------
    if (tid < NWF)        WF[tid]        = g_WF[tid];
    if (tid + 1024 < NWF) WF[tid + 1024] = g_WF[tid + 1024];
    __syncthreads();

    // ---------------- X B-fragments (this warp's half only) ----------------
    uint2 bh[4];
    {
        const float* base = SCR + site * 17;
        #pragma unroll
        for (int ks = 0; ks < 4; ks++) {
            int c0 = ks * 16 + q * 2;
            float v0 = base[(c0    ) * 276 + nn];
            float v1 = base[(c0 + 1) * 276 + nn];
            float v2 = base[(c0 + 8) * 276 + nn];
            float v3 = base[(c0 + 9) * 276 + nn];
            bh[ks] = make_uint2(pk16(v0, v1), pk16(v2, v3));
        }
    }

    // ---------------- offset rows: stage-1 on oc 12,13 -> ZOF ----------------
    {
        float* zoff = ZOF + site * 384;   // rows 0..17, stride 20, cols = n'
        #pragma unroll
        for (int oo = 0; oo < 2; oo++) {
            const int ocg = 12 + oo;
            float d0 = 0.f, d1 = 0.f, d2 = 0.f, d3 = 0.f;
            #pragma unroll
            for (int ks = 0; ks < 4; ks++)
                mma16816(d0, d1, d2, d3, WF[(ocg * 4 + ks) * 32 + lane], bh[ks]);
            int cb = tt * 8 + q * 2;
            int r0 = oo * 16 + g;
            if (r0 < 18) *(float2*)(zoff + r0 * 20 + cb) = make_float2(d0, d1);
            int r1 = r0 + 8;
            if (r1 < 18) *(float2*)(zoff + r1 * 20 + cb) = make_float2(d2, d3);
        }
    }
    __syncthreads();

    // ---------------- coefficients -> CB tables (256 threads) ----------------
    if (tid < 256) {
        int cs = tid >> 4, cn = tid & 15;
        const float* zf = ZOF + cs * 384;
        float offv[6];
        #pragma unroll
        for (int j = 0; j < 6; j++) {
            float v = BO[j];
            #pragma unroll
            for (int kk = 0; kk < 3; kk++) {
                int np = cn - 1 + kk;
                if (np >= 0 && np < 16) v += zf[(kk * 6 + j) * 20 + np];
            }
            offv[j] = v;
        }
        #pragma unroll
        for (int k = 0; k < 3; k++) {
            float px  = (float)(cn - 1 + k) + offv[2 * k + 1];
            float x0f = floorf(px);
            float fx  = px - x0f;
            int x0i = (int)x0f, x1i = x0i + 1;
            float wy = fmaxf(0.f, 1.f - fabsf(offv[2 * k]));
            float W0 = (x0i >= 0 && x0i < 16) ? (1.f - fx) * wy : 0.f;
            float W1 = (x1i >= 0 && x1i < 16) ? fx * wy : 0.f;
            int s0 = min(max(x0i, 0), 15);
            int s1 = min(max(x1i, 0), 15);
            int ci = cs * 48 + k * 16 + cn;
            CBW0[ci] = W0; CBW1[ci] = W1; CBS[ci] = (s0 << 4) | s1;
        }
    }
    __syncthreads();

    // ---------------- output accumulators (o = oc*16+g(+8), n = tt*8+2q(+1)) ----------------
    float oa[4][4];
    #pragma unroll
    for (int oc = 0; oc < 4; oc++) {
        float bd0 = BD[oc * 16 + g];
        float bd1 = BD[oc * 16 + g + 8];
        oa[oc][0] = bd0; oa[oc][1] = bd0;
        oa[oc][2] = bd1; oa[oc][3] = bd1;
    }

    uint2* EXZ = (uint2*)SCR;   // [site][oc4][tt2][lane32], 32KB

    // ---------------- main: per k3, stage-1 (4 oc) -> exchange -> stage-2 ----------------
    #pragma unroll 1
    for (int k3 = 0; k3 < 3; k3++) {
        #pragma unroll
        for (int oc = 0; oc < 4; oc++) {
            const int ocg = k3 * 4 + oc;
            float d0 = 0.f, d1 = 0.f, d2 = 0.f, d3 = 0.f;
            #pragma unroll
            for (int ks = 0; ks < 4; ks++)
                mma16816(d0, d1, d2, d3, WF[(ocg * 4 + ks) * 32 + lane], bh[ks]);
            EXZ[((site * 4 + oc) * 2 + tt) * 32 + lane] =
                make_uint2(pk16(d0, d1), pk16(d2, d3));
        }
        __syncthreads();

        // G fragments for this warp's n-half (k=16 over all 16 sites' n')
        uint2 gh, gl;
        {
            int ci = site * 48 + k3 * 16 + nn;
            float w0v = CBW0[ci], w1v = CBW1[ci];
            int s01 = CBS[ci];
            int s0v = s01 >> 4, s1v = s01 & 15;
            float gv[4];
            #pragma unroll
            for (int i = 0; i < 4; i++) {
                int s = q * 2 + (i & 1) + ((i >> 1) << 3);
                gv[i] = ((s == s0v) ? w0v : 0.f) + ((s == s1v) ? w1v : 0.f);
            }
            uint32_t h01 = pk16(gv[0], gv[1]);
            uint32_t h23 = pk16(gv[2], gv[3]);
            float2 f01 = h2f2(h01);
            float2 f23 = h2f2(h23);
            gh = make_uint2(h01, h23);
            gl = make_uint2(pk16(gv[0] - f01.x, gv[1] - f01.y),
                            pk16(gv[2] - f23.x, gv[3] - f23.y));
        }

        #pragma unroll
        for (int oc = 0; oc < 4; oc++) {
            uint2 z0 = EXZ[((site * 4 + oc) * 2 + 0) * 32 + lane];
            uint2 z1 = EXZ[((site * 4 + oc) * 2 + 1) * 32 + lane];
            uint4 za = make_uint4(z0.x, z0.y, z1.x, z1.y);
            mma16816(oa[oc][0], oa[oc][1], oa[oc][2], oa[oc][3], za, gh);
            mma16816(oa[oc][0], oa[oc][1], oa[oc][2], oa[oc][3], za, gl);
        }
        __syncthreads();   // WAR: EXZ reused next k3 / STG2 after loop
    }

    // ---------------- staged coalesced store ----------------
    {
        float* STG2 = SCR;
        #pragma unroll
        for (int oc = 0; oc < 4; oc++) {
            #pragma unroll
            for (int r = 0; r < 4; r++) {
                int o   = oc * 16 + g + ((r >> 1) << 3);
                int nn2 = tt * 8 + 2 * q + (r & 1);
                int ph  = (o & 7) | (((nn2 >> 1) & 1) << 3);
                STG2[(o * 16 + nn2) * 16 + (site ^ ph)] = oa[oc][r];
            }
        }
    }
    __syncthreads();
    {
        const float* STG2 = SCR;
        float* ob = out + xbase;
        #pragma unroll 16
        for (int idx = tid; idx < 16384; idx += 1024) {
            int s = idx & 15, on = idx >> 4;
            int o = on >> 4, nn2 = on & 15;
            int ph = (o & 7) | (((nn2 >> 1) & 1) << 3);
            ob[(long)on * HW + s] = STG2[on * 16 + (s ^ ph)];
        }
    }
}

extern "C" void kernel_launch(void* const* d_in, const int* in_sizes, int n_in,
                              void* d_out, int out_size)
{
    const float* x     = (const float*)d_in[0];
    const float* w_off = (const float*)d_in[1];
    const float* b_off = (const float*)d_in[2];
    const float* w_def = (const float*)d_in[3];
    const float* b_def = (const float*)d_in[4];
    float* out = (float*)d_out;

    cudaFuncSetAttribute(deform_hmma9_kernel,
                         cudaFuncAttributeMaxDynamicSharedMemorySize, SMEM_TOTAL);

    // prep: build weight fragments once
    deform_prep_kernel<<<7, 256>>>(w_off, w_def);
    // main: 2 (B) * 96 (H) * 6 (W/16) = 1152 CTAs, 1024 threads (32 warps/SM)
    deform_hmma9_kernel<<<1152, 1024, SMEM_TOTAL>>>(x, b_off, b_def, out);
}